// round 6
// baseline (speedup 1.0000x reference)
#include <cuda_runtime.h>
#include <math.h>

#define FULL 0xffffffffu
#define INVS10 0.31622776601683794f   // 1/sqrt(10)
#define EPS_ 1e-4f

typedef unsigned long long ull;

__device__ __forceinline__ ull PK(float lo, float hi) {
    ull r; asm("mov.b64 %0, {%1,%2};" : "=l"(r) : "f"(lo), "f"(hi)); return r;
}
__device__ __forceinline__ void UPK(ull v, float& lo, float& hi) {
    asm("mov.b64 {%0,%1}, %2;" : "=f"(lo), "=f"(hi) : "l"(v));
}
__device__ __forceinline__ ull FMA2(ull a, ull b, ull c) {
    ull d; asm("fma.rn.f32x2 %0, %1, %2, %3;" : "=l"(d) : "l"(a), "l"(b), "l"(c)); return d;
}
__device__ __forceinline__ ull MUL2(ull a, ull b) {
    ull d; asm("mul.rn.f32x2 %0, %1, %2;" : "=l"(d) : "l"(a), "l"(b)); return d;
}

// triangle enumeration (i<=j, ordered by j) + ymf column (j=8)
__constant__ unsigned char cTI[44] = {
    0, 0,1, 0,1,2, 0,1,2,3, 0,1,2,3,4, 0,1,2,3,4,5, 0,1,2,3,4,5,6,
    0,1,2,3,4,5,6,7, 0,1,2,3,4,5,6,7};
__constant__ unsigned char cTJ[44] = {
    0, 1,1, 2,2,2, 3,3,3,3, 4,4,4,4,4, 5,5,5,5,5,5, 6,6,6,6,6,6,6,
    7,7,7,7,7,7,7,7, 8,8,8,8,8,8,8,8};

// Two batches per warp: batch = half-warp. Width-16 shfl serves both batches.
struct __align__(16) WarpSmem {
    union {
        float2 A[2][16][26];            // staging [S cols 0..15 | H 16..23 | y 24]
        struct {
            float2 HY[2][9][18];        // whitened cols, col-major padded
            float2 g[2][8][9];          // Gram (mirrored); col 8 = ymf
            float2 uu[2][8];            // ymf - g*x
            float2 Mc[2][8];            // (W g)[s][s]
            float2 Wu[2][8];            // (W u)[s]
        } it;
    } s;
};

__global__ __launch_bounds__(64, 10)
void mmse_pic_kernel(const float* __restrict__ y_re, const float* __restrict__ y_im,
                     const float* __restrict__ h_re, const float* __restrict__ h_im,
                     const float* __restrict__ prior,
                     const float* __restrict__ s_re, const float* __restrict__ s_im,
                     float* __restrict__ out, int nbatch)
{
    const int warp  = threadIdx.x >> 5;
    const int lane  = threadIdx.x & 31;
    const int half  = lane >> 4;
    const int hlane = lane & 15;

    int b = blockIdx.x * 4 + warp * 2 + half;
    if (b >= nbatch) b = nbatch - 1;

    __shared__ WarpSmem ws[2];
    WarpSmem& w = ws[warp];

    // ---------------- coalesced vectorized staging of BOTH batches ----------------
    #pragma unroll
    for (int bb = 0; bb < 2; bb++) {
        int bg = blockIdx.x * 4 + warp * 2 + bb;
        if (bg >= nbatch) bg = nbatch - 1;
        const float2* sre2 = (const float2*)(s_re + (size_t)bg * 256);
        const float2* sim2 = (const float2*)(s_im + (size_t)bg * 256);
        #pragma unroll
        for (int t = lane; t < 128; t += 32) {          // S: col pairs
            int row = t >> 3, cp = t & 7;
            float2 re = sre2[t], im = sim2[t];
            *(float4*)&w.s.A[bb][row][cp * 2] = make_float4(re.x, im.x, re.y, im.y);
        }
        const float2* hre2 = (const float2*)(h_re + (size_t)bg * 128);
        const float2* him2 = (const float2*)(h_im + (size_t)bg * 128);
        #pragma unroll
        for (int t = lane; t < 64; t += 32) {           // H: col pairs
            int row = t >> 2, cp = t & 3;
            float2 re = hre2[t], im = him2[t];
            *(float4*)&w.s.A[bb][row][16 + cp * 2] = make_float4(re.x, im.x, re.y, im.y);
        }
        if (lane < 16)
            w.s.A[bb][lane][24] = make_float2(y_re[(size_t)bg * 16 + lane],
                                              y_im[(size_t)bg * 16 + lane]);
    }
    // prior LLRs (per-stream, hlane<8)
    float l0 = 0.f, l1 = 0.f, l2 = 0.f, l3 = 0.f;
    if (hlane < 8) {
        float4 p = *(const float4*)(prior + (size_t)b * 32 + hlane * 4);
        l0 = p.x; l1 = p.y; l2 = p.z; l3 = p.w;
    }
    __syncwarp();

    // ---------------- per-lane columns: vS = S col hlane, vH = [H|y] col ----------------
    ull vS[16], vH[16];
    {
        int ch = (hlane < 8) ? (16 + hlane) : 24;
        #pragma unroll
        for (int m = 0; m < 16; m++) {
            vS[m] = *(const ull*)&w.s.A[half][m][hlane];
            vH[m] = *(const ull*)&w.s.A[half][m][ch];
        }
    }
    __syncwarp();   // A dead after this

    // ---------------- forward elimination on [S | H | y] (LDL^H whitening) ----------------
    #pragma unroll
    for (int k = 0; k < 16; k++) {
        float skr, ski; UPK(vS[k], skr, ski);
        float dk = __shfl_sync(FULL, skr, k, 16);
        float invd = __fdividef(1.0f, dk);
        float rsd = rsqrtf(dk);
        ull nii = PK(-invd, -invd);
        ull wS = MUL2(vS[k], nii);
        float wsr, wsi; UPK(wS, wsr, wsi);
        ull wS2 = PK(-wsi, wsr);
        ull wH = MUL2(vH[k], nii);
        float whr, whi; UPK(wH, whr, whi);
        ull wH2 = PK(-whi, whr);
        #pragma unroll
        for (int i = k + 1; i < 16; i++) {
            float xr, xi; UPK(vS[i], xr, xi);
            float mr = __shfl_sync(FULL, xr, k, 16);
            float mi = __shfl_sync(FULL, xi, k, 16);
            ull mr2 = PK(mr, mr), mi2 = PK(mi, mi);
            vS[i] = FMA2(mr2, wS, vS[i]);
            vS[i] = FMA2(mi2, wS2, vS[i]);
            vH[i] = FMA2(mr2, wH, vH[i]);
            vH[i] = FMA2(mi2, wH2, vH[i]);
        }
        vH[k] = MUL2(vH[k], PK(rsd, rsd));
    }

    // write whitened [H | y] columns (float4)
    if (hlane < 9) {
        #pragma unroll
        for (int m = 0; m < 16; m += 2) {
            float a0, b0, a1, b1;
            UPK(vH[m], a0, b0); UPK(vH[m + 1], a1, b1);
            *(float4*)&w.s.it.HY[half][hlane][m] = make_float4(a0, b0, a1, b1);
        }
    }
    __syncwarp();

    // ---------------- Gram (Hermitian: 36 triangle + 8 ymf, mirrored) ----------
    #pragma unroll
    for (int r = 0; r < 3; r++) {
        int t = hlane + 16 * r;
        if (t < 44) {
            int i = cTI[t], j = cTJ[t];
            float re = 0.f, im = 0.f;
            #pragma unroll
            for (int m = 0; m < 16; m += 2) {
                float4 a4 = *(const float4*)&w.s.it.HY[half][i][m];
                float4 c4 = *(const float4*)&w.s.it.HY[half][j][m];
                re = fmaf(a4.x, c4.x, fmaf(a4.y, c4.y, re));
                im = fmaf(a4.x, c4.y, fmaf(-a4.y, c4.x, im));
                re = fmaf(a4.z, c4.z, fmaf(a4.w, c4.w, re));
                im = fmaf(a4.z, c4.w, fmaf(-a4.w, c4.z, im));
            }
            w.s.it.g[half][i][j] = make_float2(re, im);
            if (j < 8 && i != j)
                w.s.it.g[half][j][i] = make_float2(re, -im);
        }
    }
    __syncwarp();

    // ---------------- MMSE-PIC iterations ----------------
    float d0 = 0.f, d1 = 0.f, d2 = 0.f, d3 = 0.f;
    float pa0 = 0.f, pa1 = 0.f, pa2 = 0.f, pa3 = 0.f;

    #pragma unroll 1
    for (int iter = 0; iter < 2; iter++) {
        // (a) soft-symbol moments
        float s0 = __fdividef(1.f, 1.f + __expf(-l0));
        float s1 = __fdividef(1.f, 1.f + __expf(-l1));
        float s2 = __fdividef(1.f, 1.f + __expf(-l2));
        float s3 = __fdividef(1.f, 1.f + __expf(-l3));
        float mre = (1.f - 2.f * s0) * (1.f + 2.f * s2) * INVS10;
        float mim = (1.f - 2.f * s1) * (1.f + 2.f * s3) * INVS10;
        float var = (2.f + 8.f * (s2 + s3)) * 0.1f - (mre * mre + mim * mim);

        // (b) u = ymf - g @ x_hat
        if (hlane < 8) {
            float2 acc = w.s.it.g[half][hlane][8];
            #pragma unroll
            for (int j = 0; j < 8; j++) {
                float xrj = __shfl_sync(0x00FF00FFu, mre, j, 8);
                float xij = __shfl_sync(0x00FF00FFu, mim, j, 8);
                float2 gij = w.s.it.g[half][hlane][j];
                acc.x -= gij.x * xrj - gij.y * xij;
                acc.y -= gij.x * xij + gij.y * xrj;
            }
            w.s.it.uu[half][hlane] = acc;
        }
        __syncwarp();

        // (c) GJ columns: hlane<8 -> a_c col; hlane>=8 -> g col. c2: u at hlane 0.
        ull c1[8], c2[8];
        if (hlane < 8) {
            ull var2 = PK(var, var);
            #pragma unroll
            for (int i = 0; i < 8; i++)
                c1[i] = FMA2(*(const ull*)&w.s.it.g[half][i][hlane], var2,
                             PK((i == hlane) ? 1.f : 0.f, 0.f));
        } else {
            int j = hlane - 8;
            #pragma unroll
            for (int i = 0; i < 8; i++) c1[i] = *(const ull*)&w.s.it.g[half][i][j];
        }
        #pragma unroll
        for (int i = 0; i < 8; i++) c2[i] = 0ull;
        if (hlane == 0) {
            #pragma unroll
            for (int i = 0; i < 8; i++) c2[i] = *(const ull*)&w.s.it.uu[half][i];
        }

        // (d) 8x8 complex Gauss-Jordan
        #pragma unroll
        for (int k = 0; k < 8; k++) {
            float kr, ki; UPK(c1[k], kr, ki);
            float dk = __shfl_sync(FULL, kr, k, 16);
            float invd = __fdividef(1.f, dk);
            ull iv = PK(invd, invd);
            c1[k] = MUL2(c1[k], iv);
            c2[k] = MUL2(c2[k], iv);
            float nr, ni; UPK(c1[k], nr, ni);
            ull n1 = PK(-nr, -ni), n1b = PK(ni, -nr);
            float qr, qi; UPK(c2[k], qr, qi);
            ull n2 = PK(-qr, -qi), n2b = PK(qi, -qr);
            #pragma unroll
            for (int i = 0; i < 8; i++) {
                if (i == k) continue;
                float xr, xi; UPK(c1[i], xr, xi);
                float mr = __shfl_sync(FULL, xr, k, 16);
                float mi = __shfl_sync(FULL, xi, k, 16);
                ull mr2 = PK(mr, mr), mi2 = PK(mi, mi);
                c1[i] = FMA2(mr2, n1, c1[i]);
                c1[i] = FMA2(mi2, n1b, c1[i]);
                c2[i] = FMA2(mr2, n2, c2[i]);
                c2[i] = FMA2(mi2, n2b, c2[i]);
            }
        }

        // (e) extract Mc_s = (Wg)[s][s] and Wu
        if (hlane >= 8) {
            int s2i = hlane - 8;
            ull sel = 0ull;
            #pragma unroll
            for (int q = 0; q < 8; q++) if (q == s2i) sel = c1[q];
            *(ull*)&w.s.it.Mc[half][s2i] = sel;
        }
        if (hlane == 0) {
            #pragma unroll
            for (int s = 0; s < 8; s++) *(ull*)&w.s.it.Wu[half][s] = c2[s];
        }
        __syncwarp();

        // (f) finalize + separable max-log demap
        if (hlane < 8) {
            float2 Mc = w.s.it.Mc[half][hlane];
            float2 Wu = w.s.it.Wu[half][hlane];
            float mu = Mc.x;
            float vr = Wu.x + mre * Mc.x - mim * Mc.y;
            float vi = Wu.y + mre * Mc.y + mim * Mc.x;
            float invmu = __fdividef(1.f, mu);
            float xr_ = vr * invmu, xi_ = vi * invmu;
            float rho = mu * __fdividef(1.f, fmaxf(1.f - var * mu, EPS_));

            float q1 = rho * 0.1f;
            float c1d = 2.f * INVS10 * rho * xr_;
            float RE00 =        c1d -       q1;
            float RE01 =  3.f * c1d - 9.f * q1 + l2;
            float RE10 =       -c1d -       q1 + l0;
            float RE11 = -3.f * c1d - 9.f * q1 + l0 + l2;
            d0 = fmaxf(RE10, RE11) - fmaxf(RE00, RE01);
            d2 = fmaxf(RE01, RE11) - fmaxf(RE00, RE10);
            float c2d = 2.f * INVS10 * rho * xi_;
            float IM00 =        c2d -       q1;
            float IM01 =  3.f * c2d - 9.f * q1 + l3;
            float IM10 =       -c2d -       q1 + l1;
            float IM11 = -3.f * c2d - 9.f * q1 + l1 + l3;
            d1 = fmaxf(IM10, IM11) - fmaxf(IM00, IM01);
            d3 = fmaxf(IM01, IM11) - fmaxf(IM00, IM10);
        }

        if (iter == 0) {
            pa0 = d0; pa1 = d1; pa2 = d2; pa3 = d3;
            l0 = d0; l1 = d1; l2 = d2; l3 = d3;
        }
    }

    // ---------------- extrinsic output ----------------
    if (hlane < 8) {
        float4 o = make_float4(d0 - pa0, d1 - pa1, d2 - pa2, d3 - pa3);
        *(float4*)(out + (size_t)b * 32 + hlane * 4) = o;
    }
}

extern "C" void kernel_launch(void* const* d_in, const int* in_sizes, int n_in,
                              void* d_out, int out_size)
{
    const float* y_re  = (const float*)d_in[0];
    const float* y_im  = (const float*)d_in[1];
    const float* h_re  = (const float*)d_in[2];
    const float* h_im  = (const float*)d_in[3];
    const float* prior = (const float*)d_in[4];
    const float* s_re  = (const float*)d_in[5];
    const float* s_im  = (const float*)d_in[6];
    float* out = (float*)d_out;

    int nbatch = in_sizes[0] / 16;
    int blocks = (nbatch + 3) / 4;      // 4 batches per 64-thread block
    mmse_pic_kernel<<<blocks, 64>>>(y_re, y_im, h_re, h_im, prior,
                                    s_re, s_im, out, nbatch);
}